// round 11
// baseline (speedup 1.0000x reference)
#include <cuda_runtime.h>
#include <math.h>

#define Bq 32
#define Nn 256
#define WMw 64
#define Rr 4
#define Hh 512
#define Dd 512
#define Tt 128
#define IFACE 471
#define EPSf 1e-6f
#define G4H 2048   // 4*H
#define KIN 768    // D + R*WM

// -------- persistent state (device globals; no dynamic alloc) --------
__device__ float g_h[Bq*Hh];
__device__ float g_c[Bq*Hh];
__device__ float g_M[Bq*Nn*WMw];
__device__ float g_usage[Bq*Nn];
__device__ float g_rw[Bq*Rr*Nn];
__device__ float g_ww[Bq*Nn];
__device__ float g_prec[Bq*Nn];
__device__ float g_link[Bq*Nn*Nn];
__device__ float g_rvec[Bq*Rr*WMw];
__device__ float g_gpart[4*Bq*G4H];
__device__ float g_z[Bq*IFACE];
__device__ float g_outpre[Bq*Dd];
__device__ float g_invMn[Bq*Nn];

__device__ __forceinline__ float sigm(float x){ return 1.f/(1.f+expf(-x)); }
__device__ __forceinline__ float softplusf(float x){ return fmaxf(x,0.f) + log1pf(expf(-fabsf(x))); }
__device__ __forceinline__ float wred(float v){
  #pragma unroll
  for (int o=16;o>0;o>>=1) v += __shfl_xor_sync(0xffffffffu, v, o);
  return v;
}

// -------- init --------
__global__ void k_init(){
  int i = blockIdx.x*blockDim.x + threadIdx.x;
  int stride = gridDim.x*blockDim.x;
  for (int j=i; j<Bq*Nn*Nn; j+=stride) g_link[j]=0.f;
  for (int j=i; j<Bq*Nn*WMw; j+=stride) g_M[j]=EPSf;
  for (int j=i; j<Bq*Hh; j+=stride){ g_h[j]=0.f; g_c[j]=0.f; }
  for (int j=i; j<Bq*Nn; j+=stride){ g_usage[j]=0.f; g_ww[j]=0.f; g_prec[j]=0.f; }
  for (int j=i; j<Bq*Rr*Nn; j+=stride) g_rw[j]=0.f;
  for (int j=i; j<Bq*Rr*WMw; j+=stride) g_rvec[j]=0.f;
}

// -------- K1: gates GEMM (split-K=4, partials) --------
// grid (128, 4), block 256. col tile 16 (tid&15), 16 batch groups x 2 batches.
__global__ void k_gates(const float* __restrict__ emb,
                        const float* __restrict__ Wx,
                        const float* __restrict__ Wh, int t){
  const int col = blockIdx.x*16 + (threadIdx.x & 15);
  const int bg  = threadIdx.x >> 4;          // 0..15 -> batches bg*2, bg*2+1
  const int k0  = blockIdx.y*320;
  __shared__ float xs[32][33];
  float acc0=0.f, acc1=0.f;

  for (int kk0=0; kk0<320; kk0+=32){
    const int kbase = k0 + kk0;
    for (int i=threadIdx.x; i<1024; i+=256){
      int kk = i & 31, b = i >> 5;
      int k = kbase + kk;
      float v;
      if (k < Dd)        v = emb[((size_t)t*Bq + b)*Dd + k];
      else if (k < KIN)  v = g_rvec[b*Rr*WMw + (k - Dd)];
      else               v = g_h[b*Hh + (k - KIN)];
      xs[kk][b] = v;
    }
    __syncthreads();
    const float* wbase = (kbase < KIN) ? (Wx + (size_t)kbase*G4H)
                                       : (Wh + (size_t)(kbase-KIN)*G4H);
    #pragma unroll
    for (int kk=0; kk<32; kk++){
      float w = wbase[(size_t)kk*G4H + col];
      acc0 = fmaf(w, xs[kk][bg*2+0], acc0);
      acc1 = fmaf(w, xs[kk][bg*2+1], acc1);
    }
    __syncthreads();
  }
  float* gp = g_gpart + (size_t)blockIdx.y*Bq*G4H;
  gp[(bg*2+0)*G4H + col] = acc0;
  gp[(bg*2+1)*G4H + col] = acc1;
}

// -------- K2: LSTM pointwise --------
__global__ void k_lstm(const float* __restrict__ b_lstm){
  int idx = blockIdx.x*256 + threadIdx.x;   // 0..16383
  int b = idx >> 9, j = idx & 511;
  float g4[4];
  #pragma unroll
  for (int g=0; g<4; g++){
    int col = g*Hh + j;
    float v = b_lstm[col];
    #pragma unroll
    for (int ks=0; ks<4; ks++) v += g_gpart[(size_t)ks*Bq*G4H + b*G4H + col];
    g4[g] = v;
  }
  float i_ = sigm(g4[0]), f_ = sigm(g4[1]), gg = tanhf(g4[2]), o_ = sigm(g4[3]);
  float c = f_*g_c[b*Hh+j] + i_*gg;
  g_c[b*Hh+j] = c;
  g_h[b*Hh+j] = o_*tanhf(c);
}

// -------- K3: z = h@W_iface + b ; out_pre = h@W_pre + b_pre --------
// grid 62, block 256. col = bx*16 + (tid&15), 16 batch groups x 2 batches.
__global__ void k_iface(const float* __restrict__ Wif, const float* __restrict__ bif,
                        const float* __restrict__ Wpre, const float* __restrict__ bpre){
  const int col = blockIdx.x*16 + (threadIdx.x & 15);
  const int bg = threadIdx.x >> 4;
  const bool valid = (col < 983);
  const bool is_z = (col < IFACE);
  __shared__ float hs[32][33];
  float acc0 = 0.f, acc1 = 0.f;
  for (int kk0=0; kk0<Hh; kk0+=32){
    for (int i=threadIdx.x; i<1024; i+=256){
      int kk = i & 31, bb = i >> 5;
      hs[kk][bb] = g_h[bb*Hh + kk0 + kk];
    }
    __syncthreads();
    if (valid){
      #pragma unroll
      for (int kk=0; kk<32; kk++){
        float w = is_z ? Wif[(size_t)(kk0+kk)*IFACE + col]
                       : Wpre[(size_t)(kk0+kk)*Dd + (col - IFACE)];
        acc0 = fmaf(w, hs[kk][bg*2+0], acc0);
        acc1 = fmaf(w, hs[kk][bg*2+1], acc1);
      }
    }
    __syncthreads();
  }
  if (valid){
    if (is_z){
      float bb = bif[col];
      g_z[(bg*2+0)*IFACE + col] = acc0 + bb;
      g_z[(bg*2+1)*IFACE + col] = acc1 + bb;
    } else {
      int c2 = col - IFACE;
      float bb = bpre[c2];
      g_outpre[(bg*2+0)*Dd + c2] = acc0 + bb;
      g_outpre[(bg*2+1)*Dd + c2] = acc1 + bb;
    }
  }
}

// -------- K4: fused usage/alloc/ww + link + prec + M update + norms --------
// grid 32 (batch), block 256
__global__ void k_memwrite(){
  const int b = blockIdx.x, tid = threadIdx.x;
  const int lane = tid & 31, wid = tid >> 5;
  const float* zb = g_z + b*IFACE;
  __shared__ float s_wk[WMw], s_ev[WMw], s_wv[WMw];
  __shared__ float s_a[Nn], s_red[Nn], s_u[Nn], s_alloc[Nn], s_ww[Nn], s_pr[Nn];
  __shared__ int s_idx[Nn];

  // usage update (OLD ww, OLD rw, current free gates)
  float ret = 1.f;
  #pragma unroll
  for (int r=0; r<Rr; r++){
    float fr = sigm(zb[453+r]);
    ret *= 1.f - fr * g_rw[(b*Rr+r)*Nn + tid];
  }
  float u = g_usage[b*Nn+tid], wo = g_ww[b*Nn+tid];
  u = (u + wo - u*wo)*ret;
  g_usage[b*Nn+tid] = u;

  if (tid < WMw){
    s_wk[tid] = zb[260+tid];
    s_ev[tid] = sigm(zb[325+tid]);
    s_wv[tid] = zb[389+tid];
  }
  s_pr[tid] = g_prec[b*Nn+tid];
  __syncthreads();

  // write-content scores: warp-cooperative row dots over OLD M (coalesced)
  float k2 = 0.f;
  #pragma unroll
  for (int w=0; w<WMw; w++) k2 = fmaf(s_wk[w], s_wk[w], k2);
  float invk = 1.f/fmaxf(sqrtf(k2), EPSf);
  float wstr = 1.f + softplusf(zb[324]);
  const float* Mb = g_M + (size_t)b*Nn*WMw;
  for (int m=0; m<32; m++){
    int n = wid*32 + m;
    const float* Mr = Mb + n*WMw;
    float mv0 = Mr[lane], mv1 = Mr[lane+32];
    float d  = fmaf(mv0, s_wk[lane], mv1*s_wk[lane+32]);
    float m2 = fmaf(mv0, mv0, mv1*mv1);
    d = wred(d); m2 = wred(m2);
    if (lane == 0) s_a[n] = wstr * d * invk / fmaxf(sqrtf(m2), EPSf);
  }
  __syncthreads();

  // softmax over content scores
  float a = s_a[tid];
  s_red[tid] = a; __syncthreads();
  for (int s=128; s>0; s>>=1){ if (tid<s) s_red[tid] = fmaxf(s_red[tid], s_red[tid+s]); __syncthreads(); }
  float mx = s_red[0]; __syncthreads();
  float e = expf(a - mx); s_red[tid] = e; __syncthreads();
  for (int s=128; s>0; s>>=1){ if (tid<s) s_red[tid] += s_red[tid+s]; __syncthreads(); }
  float cwn = e / s_red[0];
  __syncthreads();

  // stable ascending bitonic sort on (usage, idx)
  s_u[tid] = u; s_idx[tid] = tid; __syncthreads();
  for (int k=2; k<=Nn; k<<=1)
    for (int j=k>>1; j>0; j>>=1){
      int ixj = tid ^ j;
      if (ixj > tid){
        float ua = s_u[tid], ub = s_u[ixj];
        int ia = s_idx[tid], ib = s_idx[ixj];
        bool gt = (ua > ub) || (ua == ub && ia > ib);
        bool up = ((tid & k) == 0);
        if (gt == up){ s_u[tid]=ub; s_u[ixj]=ua; s_idx[tid]=ib; s_idx[ixj]=ia; }
      }
      __syncthreads();
    }

  // inclusive product scan -> exclusive
  s_red[tid] = s_u[tid]; __syncthreads();
  for (int off=1; off<Nn; off<<=1){
    float v = s_red[tid];
    if (tid >= off) v *= s_red[tid-off];
    __syncthreads();
    s_red[tid] = v; __syncthreads();
  }
  float excl = (tid > 0) ? s_red[tid-1] : 1.f;
  float asrt = (1.f - s_u[tid]) * excl;
  s_alloc[s_idx[tid]] = asrt;
  __syncthreads();

  // ww + sum(ww)
  float ag = sigm(zb[457]), wg = sigm(zb[458]);
  float wwn = wg*(ag*s_alloc[tid] + (1.f-ag)*cwn);
  s_ww[tid] = wwn;
  g_ww[b*Nn+tid] = wwn;
  s_red[tid] = wwn; __syncthreads();
  for (int s=128; s>0; s>>=1){ if (tid<s) s_red[tid] += s_red[tid+s]; __syncthreads(); }
  float wwsum = s_red[0];
  __syncthreads();

  // link update (thread = column j, loop rows; coalesced, unroll 4)
  float* Lb = g_link + (size_t)b*Nn*Nn;
  float wj = wwn, prj = s_pr[tid];
  for (int i0=0; i0<Nn; i0+=4){
    float v[4];
    #pragma unroll
    for (int q=0; q<4; q++) v[q] = Lb[(size_t)(i0+q)*Nn + tid];
    #pragma unroll
    for (int q=0; q<4; q++){
      int i = i0 + q;
      float wi = s_ww[i];
      float nv = (1.f - wi - wj)*v[q] + wi*prj;
      Lb[(size_t)i*Nn + tid] = (i == tid) ? 0.f : nv;
    }
  }

  // precedence update (after link consumed old prec)
  g_prec[b*Nn+tid] = (1.f - wwsum)*prj + wwn;

  // M update: thread handles (row = (tid>>6)+4p, w = tid&63) -> coalesced
  float* Mw = g_M + (size_t)b*Nn*WMw;
  int w = tid & 63;
  #pragma unroll
  for (int p=0; p<64; p++){
    int idx = tid + p*256;
    int row = idx >> 6;
    float wwr = s_ww[row];
    Mw[idx] = Mw[idx]*(1.f - wwr*s_ev[w]) + wwr*s_wv[w];
  }
  __syncthreads();

  // M row inverse norms (warp-cooperative, coalesced)
  for (int m=0; m<32; m++){
    int n = wid*32 + m;
    const float* Mr = Mw + n*WMw;
    float mv0 = Mr[lane], mv1 = Mr[lane+32];
    float s2 = wred(fmaf(mv0, mv0, mv1*mv1));
    if (lane == 0) g_invMn[b*Nn+n] = 1.f/fmaxf(sqrtf(s2), EPSf);
  }
}

// -------- K5: fused read (all 4 heads) + rvec + output GEMM --------
// grid 32 (batch), block 256
__global__ void k_readout(const float* __restrict__ Wrout, float* __restrict__ out, int t){
  const int b = blockIdx.x, tid = threadIdx.x;
  const int lane = tid & 31, wid = tid >> 5;
  const float* zb = g_z + b*IFACE;
  __shared__ float s_rwo[Rr][Nn], s_key[Rr][WMw], s_sc[Rr][Nn];
  __shared__ float s_r4[Rr][Nn+4];
  __shared__ float s_fw[Rr][Nn], s_rwn[Rr][Nn], s_part[Rr][4][WMw], s_rv[Nn];

  #pragma unroll
  for (int r=0; r<Rr; r++) s_rwo[r][tid] = g_rw[(b*Rr+r)*Nn + tid];
  { int r = tid >> 6, w = tid & 63; s_key[r][w] = zb[r*WMw + w]; }
  __syncthreads();

  // beta / ||key|| per head
  float bk[Rr];
  #pragma unroll
  for (int r=0; r<Rr; r++){
    float k2 = 0.f;
    #pragma unroll
    for (int w=0; w<WMw; w++){ float kv = s_key[r][w]; k2 = fmaf(kv, kv, k2); }
    bk[r] = (1.f + softplusf(zb[256+r])) / fmaxf(sqrtf(k2), EPSf);
  }

  // content dots: warp-cooperative rows over (new) M, 4 heads per pass
  const float* Mb = g_M + (size_t)b*Nn*WMw;
  for (int m=0; m<32; m++){
    int n = wid*32 + m;
    const float* Mr = Mb + n*WMw;
    float mv0 = Mr[lane], mv1 = Mr[lane+32];
    float d0 = fmaf(mv0, s_key[0][lane], mv1*s_key[0][lane+32]);
    float d1 = fmaf(mv0, s_key[1][lane], mv1*s_key[1][lane+32]);
    float d2 = fmaf(mv0, s_key[2][lane], mv1*s_key[2][lane+32]);
    float d3 = fmaf(mv0, s_key[3][lane], mv1*s_key[3][lane+32]);
    d0 = wred(d0); d1 = wred(d1); d2 = wred(d2); d3 = wred(d3);
    if (lane == 0){
      float im = g_invMn[b*Nn+n];
      s_sc[0][n] = bk[0]*d0*im;
      s_sc[1][n] = bk[1]*d1*im;
      s_sc[2][n] = bk[2]*d2*im;
      s_sc[3][n] = bk[3]*d3*im;
    }
  }
  __syncthreads();

  // batched 4-way softmax
  #pragma unroll
  for (int r=0; r<Rr; r++) s_r4[r][tid] = s_sc[r][tid];
  __syncthreads();
  for (int s=128; s>0; s>>=1){
    if (tid < s){
      #pragma unroll
      for (int r=0; r<Rr; r++) s_r4[r][tid] = fmaxf(s_r4[r][tid], s_r4[r][tid+s]);
    }
    __syncthreads();
  }
  float e4[Rr];
  #pragma unroll
  for (int r=0; r<Rr; r++) e4[r] = expf(s_sc[r][tid] - s_r4[r][0]);
  __syncthreads();
  #pragma unroll
  for (int r=0; r<Rr; r++) s_r4[r][tid] = e4[r];
  __syncthreads();
  for (int s=128; s>0; s>>=1){
    if (tid < s){
      #pragma unroll
      for (int r=0; r<Rr; r++) s_r4[r][tid] += s_r4[r][tid+s];
    }
    __syncthreads();
  }
  float cr[Rr];
  #pragma unroll
  for (int r=0; r<Rr; r++) cr[r] = e4[r] / s_r4[r][0];

  // bw: thread = column tid, stream link rows (coalesced, unroll 8)
  const float* Lb = g_link + (size_t)b*Nn*Nn;
  float bw0=0.f, bw1=0.f, bw2=0.f, bw3=0.f;
  for (int i0=0; i0<Nn; i0+=8){
    float v[8];
    #pragma unroll
    for (int q=0; q<8; q++) v[q] = Lb[(size_t)(i0+q)*Nn + tid];
    #pragma unroll
    for (int q=0; q<8; q++){
      bw0 = fmaf(v[q], s_rwo[0][i0+q], bw0);
      bw1 = fmaf(v[q], s_rwo[1][i0+q], bw1);
      bw2 = fmaf(v[q], s_rwo[2][i0+q], bw2);
      bw3 = fmaf(v[q], s_rwo[3][i0+q], bw3);
    }
  }

  // fw: warp-cooperative rows (coalesced), 4 heads
  for (int m=0; m<32; m++){
    int n = wid*32 + m;
    const float* Lr = Lb + (size_t)n*Nn;
    float p0=0.f, p1=0.f, p2=0.f, p3=0.f;
    #pragma unroll
    for (int c=0; c<8; c++){
      float lv = Lr[lane + 32*c];
      p0 = fmaf(lv, s_rwo[0][lane+32*c], p0);
      p1 = fmaf(lv, s_rwo[1][lane+32*c], p1);
      p2 = fmaf(lv, s_rwo[2][lane+32*c], p2);
      p3 = fmaf(lv, s_rwo[3][lane+32*c], p3);
    }
    p0 = wred(p0); p1 = wred(p1); p2 = wred(p2); p3 = wred(p3);
    if (lane == 0){ s_fw[0][n]=p0; s_fw[1][n]=p1; s_fw[2][n]=p2; s_fw[3][n]=p3; }
  }
  __syncthreads();

  // modes softmax + combine + store new rw
  float bwv[Rr] = {bw0, bw1, bw2, bw3};
  #pragma unroll
  for (int r=0; r<Rr; r++){
    float z0 = zb[459+3*r], z1 = zb[460+3*r], z2 = zb[461+3*r];
    float mm = fmaxf(z0, fmaxf(z1, z2));
    float e0 = expf(z0-mm), e1 = expf(z1-mm), e2 = expf(z2-mm);
    float inv = 1.f/(e0+e1+e2);
    float rwn = (e0*bwv[r] + e1*cr[r] + e2*s_fw[r][tid])*inv;
    g_rw[(b*Rr+r)*Nn + tid] = rwn;
    s_rwn[r][tid] = rwn;
  }
  __syncthreads();

  // rvec = rw @ M (partials over 4 n-quarters), 4 heads per M load
  {
    int w = tid & 63, q = tid >> 6;
    float p0=0.f, p1=0.f, p2=0.f, p3=0.f;
    for (int n=q*64; n<q*64+64; n++){
      float mv = Mb[(size_t)n*WMw + w];
      p0 = fmaf(s_rwn[0][n], mv, p0);
      p1 = fmaf(s_rwn[1][n], mv, p1);
      p2 = fmaf(s_rwn[2][n], mv, p2);
      p3 = fmaf(s_rwn[3][n], mv, p3);
    }
    s_part[0][q][w]=p0; s_part[1][q][w]=p1; s_part[2][q][w]=p2; s_part[3][q][w]=p3;
  }
  __syncthreads();
  {
    int r = tid >> 6, w = tid & 63;
    float v = s_part[r][0][w] + s_part[r][1][w] + s_part[r][2][w] + s_part[r][3][w];
    s_rv[tid] = v;
    g_rvec[b*Rr*WMw + tid] = v;
  }
  __syncthreads();

  // out = out_pre + rvec @ W_rout  (thread: cols tid and tid+256)
  float acc0 = g_outpre[b*Dd + tid];
  float acc1 = g_outpre[b*Dd + 256 + tid];
  #pragma unroll 4
  for (int k=0; k<Nn; k++){
    float rv = s_rv[k];
    acc0 = fmaf(rv, Wrout[(size_t)k*Dd + tid], acc0);
    acc1 = fmaf(rv, Wrout[(size_t)k*Dd + 256 + tid], acc1);
  }
  out[((size_t)t*Bq + b)*Dd + tid] = acc0;
  out[((size_t)t*Bq + b)*Dd + 256 + tid] = acc1;
}

// -------- launch --------
extern "C" void kernel_launch(void* const* d_in, const int* in_sizes, int n_in,
                              void* d_out, int out_size){
  const float* emb   = (const float*)d_in[0];
  const float* Wx    = (const float*)d_in[1];
  const float* Wh    = (const float*)d_in[2];
  const float* bl    = (const float*)d_in[3];
  const float* Wpre  = (const float*)d_in[4];
  const float* bpre  = (const float*)d_in[5];
  const float* Wif   = (const float*)d_in[6];
  const float* bif   = (const float*)d_in[7];
  const float* Wrout = (const float*)d_in[8];
  float* out = (float*)d_out;

  k_init<<<2048, 256>>>();
  for (int t=0; t<Tt; t++){
    k_gates<<<dim3(128,4), 256>>>(emb, Wx, Wh, t);
    k_lstm<<<64, 256>>>(bl);
    k_iface<<<62, 256>>>(Wif, bif, Wpre, bpre);
    k_memwrite<<<32, 256>>>();
    k_readout<<<32, 256>>>(Wrout, out, t);
  }
}

// round 12
// speedup vs baseline: 1.0239x; 1.0239x over previous
#include <cuda_runtime.h>
#include <math.h>

#define Bq 32
#define Nn 256
#define WMw 64
#define Rr 4
#define Hh 512
#define Dd 512
#define Tt 128
#define IFACE 471
#define EPSf 1e-6f
#define G4H 2048   // 4*H
#define KIN 768    // D + R*WM

// -------- persistent state (device globals; no dynamic alloc) --------
__device__ float g_h[Bq*Hh];
__device__ float g_c[Bq*Hh];
__device__ float g_M[Bq*Nn*WMw];
__device__ float g_usage[Bq*Nn];
__device__ float g_rw[Bq*Rr*Nn];
__device__ float g_ww[Bq*Nn];
__device__ float g_prec[Bq*Nn];
__device__ float g_link[Bq*Nn*Nn];
__device__ float g_rvec[Bq*Rr*WMw];
__device__ float g_gpart[4*Bq*G4H];
__device__ float g_z[Bq*IFACE];
__device__ float g_outpre[Bq*Dd];
__device__ float g_invMn[Bq*Nn];

__device__ __forceinline__ float sigm(float x){ return 1.f/(1.f+expf(-x)); }
__device__ __forceinline__ float softplusf(float x){ return fmaxf(x,0.f) + log1pf(expf(-fabsf(x))); }
__device__ __forceinline__ float wred(float v){
  #pragma unroll
  for (int o=16;o>0;o>>=1) v += __shfl_xor_sync(0xffffffffu, v, o);
  return v;
}

// -------- init --------
__global__ void k_init(){
  int i = blockIdx.x*blockDim.x + threadIdx.x;
  int stride = gridDim.x*blockDim.x;
  for (int j=i; j<Bq*Nn*Nn; j+=stride) g_link[j]=0.f;
  for (int j=i; j<Bq*Nn*WMw; j+=stride) g_M[j]=EPSf;
  for (int j=i; j<Bq*Hh; j+=stride){ g_h[j]=0.f; g_c[j]=0.f; }
  for (int j=i; j<Bq*Nn; j+=stride){ g_usage[j]=0.f; g_ww[j]=0.f; g_prec[j]=0.f; }
  for (int j=i; j<Bq*Rr*Nn; j+=stride) g_rw[j]=0.f;
  for (int j=i; j<Bq*Rr*WMw; j+=stride) g_rvec[j]=0.f;
}

// -------- K1: gates GEMM (split-K=4, partials) --------
// grid (128, 4), block 256. col tile 16 (tid&15), 16 batch groups x 2 batches.
__global__ void k_gates(const float* __restrict__ emb,
                        const float* __restrict__ Wx,
                        const float* __restrict__ Wh, int t){
  const int col = blockIdx.x*16 + (threadIdx.x & 15);
  const int bg  = threadIdx.x >> 4;          // 0..15 -> batches bg*2, bg*2+1
  const int k0  = blockIdx.y*320;
  __shared__ float xs[32][33];
  float acc0=0.f, acc1=0.f;

  for (int kk0=0; kk0<320; kk0+=32){
    const int kbase = k0 + kk0;
    for (int i=threadIdx.x; i<1024; i+=256){
      int kk = i & 31, b = i >> 5;
      int k = kbase + kk;
      float v;
      if (k < Dd)        v = emb[((size_t)t*Bq + b)*Dd + k];
      else if (k < KIN)  v = g_rvec[b*Rr*WMw + (k - Dd)];
      else               v = g_h[b*Hh + (k - KIN)];
      xs[kk][b] = v;
    }
    __syncthreads();
    const float* wbase = (kbase < KIN) ? (Wx + (size_t)kbase*G4H)
                                       : (Wh + (size_t)(kbase-KIN)*G4H);
    #pragma unroll
    for (int kk=0; kk<32; kk++){
      float w = wbase[(size_t)kk*G4H + col];
      acc0 = fmaf(w, xs[kk][bg*2+0], acc0);
      acc1 = fmaf(w, xs[kk][bg*2+1], acc1);
    }
    __syncthreads();
  }
  float* gp = g_gpart + (size_t)blockIdx.y*Bq*G4H;
  gp[(bg*2+0)*G4H + col] = acc0;
  gp[(bg*2+1)*G4H + col] = acc1;
}

// -------- K2: LSTM pointwise --------
__global__ void k_lstm(const float* __restrict__ b_lstm){
  int idx = blockIdx.x*256 + threadIdx.x;   // 0..16383
  int b = idx >> 9, j = idx & 511;
  float g4[4];
  #pragma unroll
  for (int g=0; g<4; g++){
    int col = g*Hh + j;
    float v = b_lstm[col];
    #pragma unroll
    for (int ks=0; ks<4; ks++) v += g_gpart[(size_t)ks*Bq*G4H + b*G4H + col];
    g4[g] = v;
  }
  float i_ = sigm(g4[0]), f_ = sigm(g4[1]), gg = tanhf(g4[2]), o_ = sigm(g4[3]);
  float c = f_*g_c[b*Hh+j] + i_*gg;
  g_c[b*Hh+j] = c;
  g_h[b*Hh+j] = o_*tanhf(c);
}

// -------- K3: z = h@W_iface + b ; out_pre = h@W_pre + b_pre --------
// grid 62, block 256. col = bx*16 + (tid&15), 16 batch groups x 2 batches.
__global__ void k_iface(const float* __restrict__ Wif, const float* __restrict__ bif,
                        const float* __restrict__ Wpre, const float* __restrict__ bpre){
  const int col = blockIdx.x*16 + (threadIdx.x & 15);
  const int bg = threadIdx.x >> 4;
  const bool valid = (col < 983);
  const bool is_z = (col < IFACE);
  __shared__ float hs[32][33];
  float acc0 = 0.f, acc1 = 0.f;
  for (int kk0=0; kk0<Hh; kk0+=32){
    for (int i=threadIdx.x; i<1024; i+=256){
      int kk = i & 31, bb = i >> 5;
      hs[kk][bb] = g_h[bb*Hh + kk0 + kk];
    }
    __syncthreads();
    if (valid){
      #pragma unroll
      for (int kk=0; kk<32; kk++){
        float w = is_z ? Wif[(size_t)(kk0+kk)*IFACE + col]
                       : Wpre[(size_t)(kk0+kk)*Dd + (col - IFACE)];
        acc0 = fmaf(w, hs[kk][bg*2+0], acc0);
        acc1 = fmaf(w, hs[kk][bg*2+1], acc1);
      }
    }
    __syncthreads();
  }
  if (valid){
    if (is_z){
      float bb = bif[col];
      g_z[(bg*2+0)*IFACE + col] = acc0 + bb;
      g_z[(bg*2+1)*IFACE + col] = acc1 + bb;
    } else {
      int c2 = col - IFACE;
      float bb = bpre[c2];
      g_outpre[(bg*2+0)*Dd + c2] = acc0 + bb;
      g_outpre[(bg*2+1)*Dd + c2] = acc1 + bb;
    }
  }
}

// -------- K4: fused usage/alloc/ww + link + prec + M update + norms --------
// grid 32 (batch), block 256
__global__ void k_memwrite(){
  const int b = blockIdx.x, tid = threadIdx.x;
  const int lane = tid & 31, wid = tid >> 5;
  const float* zb = g_z + b*IFACE;
  __shared__ float s_wk[WMw], s_ev[WMw], s_wv[WMw];
  __shared__ float s_a[Nn], s_red[Nn], s_u[Nn], s_alloc[Nn], s_ww[Nn], s_pr[Nn];
  __shared__ int s_idx[Nn];

  // usage update (OLD ww, OLD rw, current free gates)
  float ret = 1.f;
  #pragma unroll
  for (int r=0; r<Rr; r++){
    float fr = sigm(zb[453+r]);
    ret *= 1.f - fr * g_rw[(b*Rr+r)*Nn + tid];
  }
  float u = g_usage[b*Nn+tid], wo = g_ww[b*Nn+tid];
  u = (u + wo - u*wo)*ret;
  g_usage[b*Nn+tid] = u;

  if (tid < WMw){
    s_wk[tid] = zb[260+tid];
    s_ev[tid] = sigm(zb[325+tid]);
    s_wv[tid] = zb[389+tid];
  }
  s_pr[tid] = g_prec[b*Nn+tid];
  __syncthreads();

  // write-content scores: warp-cooperative row dots over OLD M (coalesced)
  float k2 = 0.f;
  #pragma unroll
  for (int w=0; w<WMw; w++) k2 = fmaf(s_wk[w], s_wk[w], k2);
  float invk = 1.f/fmaxf(sqrtf(k2), EPSf);
  float wstr = 1.f + softplusf(zb[324]);
  const float* Mb = g_M + (size_t)b*Nn*WMw;
  for (int m=0; m<32; m++){
    int n = wid*32 + m;
    const float* Mr = Mb + n*WMw;
    float mv0 = Mr[lane], mv1 = Mr[lane+32];
    float d  = fmaf(mv0, s_wk[lane], mv1*s_wk[lane+32]);
    float m2 = fmaf(mv0, mv0, mv1*mv1);
    d = wred(d); m2 = wred(m2);
    if (lane == 0) s_a[n] = wstr * d * invk / fmaxf(sqrtf(m2), EPSf);
  }
  __syncthreads();

  // softmax over content scores
  float a = s_a[tid];
  s_red[tid] = a; __syncthreads();
  for (int s=128; s>0; s>>=1){ if (tid<s) s_red[tid] = fmaxf(s_red[tid], s_red[tid+s]); __syncthreads(); }
  float mx = s_red[0]; __syncthreads();
  float e = expf(a - mx); s_red[tid] = e; __syncthreads();
  for (int s=128; s>0; s>>=1){ if (tid<s) s_red[tid] += s_red[tid+s]; __syncthreads(); }
  float cwn = e / s_red[0];
  __syncthreads();

  // stable ascending bitonic sort on (usage, idx)
  s_u[tid] = u; s_idx[tid] = tid; __syncthreads();
  for (int k=2; k<=Nn; k<<=1)
    for (int j=k>>1; j>0; j>>=1){
      int ixj = tid ^ j;
      if (ixj > tid){
        float ua = s_u[tid], ub = s_u[ixj];
        int ia = s_idx[tid], ib = s_idx[ixj];
        bool gt = (ua > ub) || (ua == ub && ia > ib);
        bool up = ((tid & k) == 0);
        if (gt == up){ s_u[tid]=ub; s_u[ixj]=ua; s_idx[tid]=ib; s_idx[ixj]=ia; }
      }
      __syncthreads();
    }

  // inclusive product scan -> exclusive
  s_red[tid] = s_u[tid]; __syncthreads();
  for (int off=1; off<Nn; off<<=1){
    float v = s_red[tid];
    if (tid >= off) v *= s_red[tid-off];
    __syncthreads();
    s_red[tid] = v; __syncthreads();
  }
  float excl = (tid > 0) ? s_red[tid-1] : 1.f;
  float asrt = (1.f - s_u[tid]) * excl;
  s_alloc[s_idx[tid]] = asrt;
  __syncthreads();

  // ww + sum(ww)
  float ag = sigm(zb[457]), wg = sigm(zb[458]);
  float wwn = wg*(ag*s_alloc[tid] + (1.f-ag)*cwn);
  s_ww[tid] = wwn;
  g_ww[b*Nn+tid] = wwn;
  s_red[tid] = wwn; __syncthreads();
  for (int s=128; s>0; s>>=1){ if (tid<s) s_red[tid] += s_red[tid+s]; __syncthreads(); }
  float wwsum = s_red[0];
  __syncthreads();

  // link update (thread = column j, loop rows; coalesced, unroll 4)
  float* Lb = g_link + (size_t)b*Nn*Nn;
  float wj = wwn, prj = s_pr[tid];
  for (int i0=0; i0<Nn; i0+=4){
    float v[4];
    #pragma unroll
    for (int q=0; q<4; q++) v[q] = Lb[(size_t)(i0+q)*Nn + tid];
    #pragma unroll
    for (int q=0; q<4; q++){
      int i = i0 + q;
      float wi = s_ww[i];
      float nv = (1.f - wi - wj)*v[q] + wi*prj;
      Lb[(size_t)i*Nn + tid] = (i == tid) ? 0.f : nv;
    }
  }

  // precedence update (after link consumed old prec)
  g_prec[b*Nn+tid] = (1.f - wwsum)*prj + wwn;

  // M update: thread handles (row = (tid>>6)+4p, w = tid&63) -> coalesced
  float* Mw = g_M + (size_t)b*Nn*WMw;
  int w = tid & 63;
  #pragma unroll
  for (int p=0; p<64; p++){
    int idx = tid + p*256;
    int row = idx >> 6;
    float wwr = s_ww[row];
    Mw[idx] = Mw[idx]*(1.f - wwr*s_ev[w]) + wwr*s_wv[w];
  }
  __syncthreads();

  // M row inverse norms (warp-cooperative, coalesced)
  for (int m=0; m<32; m++){
    int n = wid*32 + m;
    const float* Mr = Mw + n*WMw;
    float mv0 = Mr[lane], mv1 = Mr[lane+32];
    float s2 = wred(fmaf(mv0, mv0, mv1*mv1));
    if (lane == 0) g_invMn[b*Nn+n] = 1.f/fmaxf(sqrtf(s2), EPSf);
  }
}

// -------- K5: fused read (all 4 heads) + rvec + output GEMM --------
// grid 32 (batch), block 256
__global__ void k_readout(const float* __restrict__ Wrout, float* __restrict__ out, int t){
  const int b = blockIdx.x, tid = threadIdx.x;
  const int lane = tid & 31, wid = tid >> 5;
  const float* zb = g_z + b*IFACE;
  __shared__ float s_rwo[Rr][Nn], s_key[Rr][WMw], s_sc[Rr][Nn];
  __shared__ float s_r4[Rr][Nn+4];
  __shared__ float s_fw[Rr][Nn], s_rwn[Rr][Nn], s_part[Rr][4][WMw], s_rv[Nn];

  #pragma unroll
  for (int r=0; r<Rr; r++) s_rwo[r][tid] = g_rw[(b*Rr+r)*Nn + tid];
  { int r = tid >> 6, w = tid & 63; s_key[r][w] = zb[r*WMw + w]; }
  __syncthreads();

  // beta / ||key|| per head
  float bk[Rr];
  #pragma unroll
  for (int r=0; r<Rr; r++){
    float k2 = 0.f;
    #pragma unroll
    for (int w=0; w<WMw; w++){ float kv = s_key[r][w]; k2 = fmaf(kv, kv, k2); }
    bk[r] = (1.f + softplusf(zb[256+r])) / fmaxf(sqrtf(k2), EPSf);
  }

  // content dots: warp-cooperative rows over (new) M, 4 heads per pass
  const float* Mb = g_M + (size_t)b*Nn*WMw;
  for (int m=0; m<32; m++){
    int n = wid*32 + m;
    const float* Mr = Mb + n*WMw;
    float mv0 = Mr[lane], mv1 = Mr[lane+32];
    float d0 = fmaf(mv0, s_key[0][lane], mv1*s_key[0][lane+32]);
    float d1 = fmaf(mv0, s_key[1][lane], mv1*s_key[1][lane+32]);
    float d2 = fmaf(mv0, s_key[2][lane], mv1*s_key[2][lane+32]);
    float d3 = fmaf(mv0, s_key[3][lane], mv1*s_key[3][lane+32]);
    d0 = wred(d0); d1 = wred(d1); d2 = wred(d2); d3 = wred(d3);
    if (lane == 0){
      float im = g_invMn[b*Nn+n];
      s_sc[0][n] = bk[0]*d0*im;
      s_sc[1][n] = bk[1]*d1*im;
      s_sc[2][n] = bk[2]*d2*im;
      s_sc[3][n] = bk[3]*d3*im;
    }
  }
  __syncthreads();

  // batched 4-way softmax
  #pragma unroll
  for (int r=0; r<Rr; r++) s_r4[r][tid] = s_sc[r][tid];
  __syncthreads();
  for (int s=128; s>0; s>>=1){
    if (tid < s){
      #pragma unroll
      for (int r=0; r<Rr; r++) s_r4[r][tid] = fmaxf(s_r4[r][tid], s_r4[r][tid+s]);
    }
    __syncthreads();
  }
  float e4[Rr];
  #pragma unroll
  for (int r=0; r<Rr; r++) e4[r] = expf(s_sc[r][tid] - s_r4[r][0]);
  __syncthreads();
  #pragma unroll
  for (int r=0; r<Rr; r++) s_r4[r][tid] = e4[r];
  __syncthreads();
  for (int s=128; s>0; s>>=1){
    if (tid < s){
      #pragma unroll
      for (int r=0; r<Rr; r++) s_r4[r][tid] += s_r4[r][tid+s];
    }
    __syncthreads();
  }
  float cr[Rr];
  #pragma unroll
  for (int r=0; r<Rr; r++) cr[r] = e4[r] / s_r4[r][0];

  // bw: thread = column tid, stream link rows (coalesced, unroll 8)
  const float* Lb = g_link + (size_t)b*Nn*Nn;
  float bw0=0.f, bw1=0.f, bw2=0.f, bw3=0.f;
  for (int i0=0; i0<Nn; i0+=8){
    float v[8];
    #pragma unroll
    for (int q=0; q<8; q++) v[q] = Lb[(size_t)(i0+q)*Nn + tid];
    #pragma unroll
    for (int q=0; q<8; q++){
      bw0 = fmaf(v[q], s_rwo[0][i0+q], bw0);
      bw1 = fmaf(v[q], s_rwo[1][i0+q], bw1);
      bw2 = fmaf(v[q], s_rwo[2][i0+q], bw2);
      bw3 = fmaf(v[q], s_rwo[3][i0+q], bw3);
    }
  }

  // fw: warp-cooperative rows (coalesced), 4 heads
  for (int m=0; m<32; m++){
    int n = wid*32 + m;
    const float* Lr = Lb + (size_t)n*Nn;
    float p0=0.f, p1=0.f, p2=0.f, p3=0.f;
    #pragma unroll
    for (int c=0; c<8; c++){
      float lv = Lr[lane + 32*c];
      p0 = fmaf(lv, s_rwo[0][lane+32*c], p0);
      p1 = fmaf(lv, s_rwo[1][lane+32*c], p1);
      p2 = fmaf(lv, s_rwo[2][lane+32*c], p2);
      p3 = fmaf(lv, s_rwo[3][lane+32*c], p3);
    }
    p0 = wred(p0); p1 = wred(p1); p2 = wred(p2); p3 = wred(p3);
    if (lane == 0){ s_fw[0][n]=p0; s_fw[1][n]=p1; s_fw[2][n]=p2; s_fw[3][n]=p3; }
  }
  __syncthreads();

  // modes softmax + combine + store new rw
  float bwv[Rr] = {bw0, bw1, bw2, bw3};
  #pragma unroll
  for (int r=0; r<Rr; r++){
    float z0 = zb[459+3*r], z1 = zb[460+3*r], z2 = zb[461+3*r];
    float mm = fmaxf(z0, fmaxf(z1, z2));
    float e0 = expf(z0-mm), e1 = expf(z1-mm), e2 = expf(z2-mm);
    float inv = 1.f/(e0+e1+e2);
    float rwn = (e0*bwv[r] + e1*cr[r] + e2*s_fw[r][tid])*inv;
    g_rw[(b*Rr+r)*Nn + tid] = rwn;
    s_rwn[r][tid] = rwn;
  }
  __syncthreads();

  // rvec = rw @ M (partials over 4 n-quarters), 4 heads per M load
  {
    int w = tid & 63, q = tid >> 6;
    float p0=0.f, p1=0.f, p2=0.f, p3=0.f;
    for (int n=q*64; n<q*64+64; n++){
      float mv = Mb[(size_t)n*WMw + w];
      p0 = fmaf(s_rwn[0][n], mv, p0);
      p1 = fmaf(s_rwn[1][n], mv, p1);
      p2 = fmaf(s_rwn[2][n], mv, p2);
      p3 = fmaf(s_rwn[3][n], mv, p3);
    }
    s_part[0][q][w]=p0; s_part[1][q][w]=p1; s_part[2][q][w]=p2; s_part[3][q][w]=p3;
  }
  __syncthreads();
  {
    int r = tid >> 6, w = tid & 63;
    float v = s_part[r][0][w] + s_part[r][1][w] + s_part[r][2][w] + s_part[r][3][w];
    s_rv[tid] = v;
    g_rvec[b*Rr*WMw + tid] = v;
  }
  __syncthreads();

  // out = out_pre + rvec @ W_rout  (thread: cols tid and tid+256)
  float acc0 = g_outpre[b*Dd + tid];
  float acc1 = g_outpre[b*Dd + 256 + tid];
  #pragma unroll 4
  for (int k=0; k<Nn; k++){
    float rv = s_rv[k];
    acc0 = fmaf(rv, Wrout[(size_t)k*Dd + tid], acc0);
    acc1 = fmaf(rv, Wrout[(size_t)k*Dd + 256 + tid], acc1);
  }
  out[((size_t)t*Bq + b)*Dd + tid] = acc0;
  out[((size_t)t*Bq + b)*Dd + 256 + tid] = acc1;
}

// -------- launch --------
extern "C" void kernel_launch(void* const* d_in, const int* in_sizes, int n_in,
                              void* d_out, int out_size){
  const float* emb   = (const float*)d_in[0];
  const float* Wx    = (const float*)d_in[1];
  const float* Wh    = (const float*)d_in[2];
  const float* bl    = (const float*)d_in[3];
  const float* Wpre  = (const float*)d_in[4];
  const float* bpre  = (const float*)d_in[5];
  const float* Wif   = (const float*)d_in[6];
  const float* bif   = (const float*)d_in[7];
  const float* Wrout = (const float*)d_in[8];
  float* out = (float*)d_out;

  k_init<<<2048, 256>>>();
  for (int t=0; t<Tt; t++){
    k_gates<<<dim3(128,4), 256>>>(emb, Wx, Wh, t);
    k_lstm<<<64, 256>>>(bl);
    k_iface<<<62, 256>>>(Wif, bif, Wpre, bpre);
    k_memwrite<<<32, 256>>>();
    k_readout<<<32, 256>>>(Wrout, out, t);
  }
}